// round 13
// baseline (speedup 1.0000x reference)
#include <cuda_runtime.h>
#include <cuda_fp16.h>
#include <cstdint>

#define Hh 768
#define Ss 128
#define Bb_ 8
#define Pp 8256            // S*(S+1)/2
#define NROWS 1024         // B*S
#define H4 192             // H/4
#define NX (NROWS * Hh)    // 786432
#define NW (Hh * Hh)       // 589824 per weight matrix
#define NX4 (NX / 4)       // 196608 float4s in X
#define NW4 (NW / 4)       // 147456 float4s per W

// fp32 activation outputs (pre-scaled by 0.5)
__device__ __align__(16) float g_A1[NX];
__device__ __align__(16) float g_A2[NX];
__device__ __align__(16) float g_Bb[NX];
__device__ __align__(16) float g_Gg[NX];
__device__ __align__(16) float g_Z[NX];     // (y - mean) * rstd (NOT scaled)

// fp16 operands (single precision term — measured rel_err 2.0e-4 < 1e-3)
__device__ __align__(16) __half g_Xf[NX];
__device__ __align__(16) __half g_Yf[NX];
__device__ __align__(16) __half g_Wf[4 * NW];

// ---------------- PTX helpers ----------------

#define CP_ASYNC16(dst, src) \
    asm volatile("cp.async.cg.shared.global [%0], [%1], 16;" \
        :: "r"(dst), "l"(src) : "memory")
#define CP_COMMIT() asm volatile("cp.async.commit_group;" ::: "memory")
#define CP_WAIT(n)  asm volatile("cp.async.wait_group %0;" :: "n"(n) : "memory")

#define LDSM4(R, addr) \
    asm volatile("ldmatrix.sync.aligned.m8n8.x4.shared.b16 {%0,%1,%2,%3}, [%4];" \
        : "=r"((R)[0]), "=r"((R)[1]), "=r"((R)[2]), "=r"((R)[3]) : "r"(addr))

#define MMA16816F(c, a, b0, b1) \
    asm volatile("mma.sync.aligned.m16n8k16.row.col.f32.f16.f16.f32 " \
        "{%0,%1,%2,%3},{%4,%5,%6,%7},{%8,%9},{%0,%1,%2,%3};" \
        : "+f"((c)[0]), "+f"((c)[1]), "+f"((c)[2]), "+f"((c)[3]) \
        : "r"((a)[0]), "r"((a)[1]), "r"((a)[2]), "r"((a)[3]), "r"(b0), "r"(b1))

// float4 -> packed fp16x4
__device__ __forceinline__ uint2 cvt4(float4 v)
{
    __half2 h0 = __float22half2_rn(make_float2(v.x, v.y));
    __half2 h1 = __float22half2_rn(make_float2(v.z, v.w));
    uint2 r;
    r.x = *(uint32_t*)&h0; r.y = *(uint32_t*)&h1;
    return r;
}

// ---------------- merged prep v4: block-uniform source mapping ---------------
// conv blocks: [0,96) X | [96,168) W0 | [168,240) W1 | [240,312) W2 | [312,384) W3
// stats blocks: [384,512)
__global__ void __launch_bounds__(256) prep_kernel(
    const float* __restrict__ x, const float* __restrict__ y,
    const float* __restrict__ catW,
    const float* __restrict__ betaW, const float* __restrict__ gammaW)
{
    const int bx = blockIdx.x;
    if (bx < 384) {
        float4 v[8];
        if (bx < 96) {
            // X: contiguous
            const int base4 = bx * 2048 + threadIdx.x;
            const float4* src = (const float4*)x;
#pragma unroll
            for (int k = 0; k < 8; ++k) v[k] = src[base4 + k * 256];
#pragma unroll
            for (int k = 0; k < 8; ++k)
                *(uint2*)(g_Xf + (size_t)(base4 + k * 256) * 4) = cvt4(v[k]);
        } else if (bx < 240) {
            // W0 (guide half) / W1 (visible half) of catW: row stride 384 f4
            const int g = (bx - 96) / 72;                 // 0 or 1
            const int base4 = ((bx - 96) - g * 72) * 2048 + threadIdx.x;
            const float4* src = (const float4*)catW + g * 192;
#pragma unroll
            for (int k = 0; k < 8; ++k) {
                const int rem4 = base4 + k * 256;
                const int r  = rem4 / 192;
                const int k4 = rem4 - r * 192;
                v[k] = src[r * 384 + k4];
            }
            __half* dst = g_Wf + (size_t)g * NW;
#pragma unroll
            for (int k = 0; k < 8; ++k)
                *(uint2*)(dst + (size_t)(base4 + k * 256) * 4) = cvt4(v[k]);
        } else {
            // W2 = betaW, W3 = gammaW: contiguous
            const int g = (bx - 240) / 72;                // 0 or 1
            const int base4 = ((bx - 240) - g * 72) * 2048 + threadIdx.x;
            const float4* src = (const float4*)(g ? gammaW : betaW);
#pragma unroll
            for (int k = 0; k < 8; ++k) v[k] = src[base4 + k * 256];
            __half* dst = g_Wf + (size_t)(2 + g) * NW;
#pragma unroll
            for (int k = 0; k < 8; ++k)
                *(uint2*)(dst + (size_t)(base4 + k * 256) * 4) = cvt4(v[k]);
        }
        return;
    }

    // stats for 8 Y rows (warp per row)
    const int rowi = (bx - 384) * 8 + (threadIdx.x >> 5);
    const int lane = threadIdx.x & 31;
    const float4* p = (const float4*)(y + (size_t)rowi * Hh);

    float4 v[6];
    float s = 0.f;
#pragma unroll
    for (int q = 0; q < 6; ++q) {
        v[q] = p[lane + 32 * q];
        s += v[q].x + v[q].y + v[q].z + v[q].w;
    }
#pragma unroll
    for (int o = 16; o; o >>= 1) s += __shfl_xor_sync(0xffffffffu, s, o);
    const float m = s * (1.0f / Hh);

    float ss = 0.f;
#pragma unroll
    for (int q = 0; q < 6; ++q) {
        float dx = v[q].x - m, dy = v[q].y - m, dz = v[q].z - m, dw = v[q].w - m;
        ss += dx * dx + dy * dy + dz * dz + dw * dw;
    }
#pragma unroll
    for (int o = 16; o; o >>= 1) ss += __shfl_xor_sync(0xffffffffu, ss, o);
    const float var = ss * (1.0f / Hh);
    float sd = var + 1e-12f;
    sd = sd * sd;                     // reference: std = (var+eps)**2
    const float rr = 1.0f / sd;

    float4* z = (float4*)(g_Z + (size_t)rowi * Hh);
#pragma unroll
    for (int q = 0; q < 6; ++q) {
        float4 o;
        o.x = (v[q].x - m) * rr; o.y = (v[q].y - m) * rr;
        o.z = (v[q].z - m) * rr; o.w = (v[q].w - m) * rr;
        z[lane + 32 * q] = o;
        const size_t eo = (size_t)rowi * Hh + (lane + 32 * q) * 4;
        *(uint2*)(g_Yf + eo) = cvt4(v[q]);
    }
}

// ---------------- HMMA fp16 GEMM: 64x128 tiles, BK=32, 3-stage cp.async ------
// stage: A[64 x 40h] = 5120 B | W[128 x 40h] = 10240 B
#define ST_W    5120
#define STAGE   15360
#define NSTAGE  3
#define SMEM_G  (NSTAGE * STAGE)

struct GemmCtx {
    uint32_t sm0;
    uint32_t offA, a_off, b_off;
    const __half *Ap, *Wp0, *Wp1;
};

__device__ __forceinline__ void issue_stage(const GemmCtx& g, int s, int kc)
{
    const uint32_t b0 = g.sm0 + s * STAGE;
    const int ko = kc * 32;
    CP_ASYNC16(b0 + g.offA,                g.Ap  + ko);
    CP_ASYNC16(b0 + ST_W + g.offA,         g.Wp0 + ko);
    CP_ASYNC16(b0 + ST_W + g.offA + 5120,  g.Wp1 + ko);
    CP_COMMIT();
}

__device__ __forceinline__ void mma_stage(const GemmCtx& g, int s, float c[2][4][4])
{
    const uint32_t base = g.sm0 + s * STAGE;
#pragma unroll
    for (int kh = 0; kh < 2; ++kh) {
        const uint32_t ao = g.a_off + kh * 32;
        const uint32_t bo = g.b_off + kh * 32;
        uint32_t A[2][4], B[2][4];
        LDSM4(A[0], base + ao);
        LDSM4(A[1], base + ao + 1280);
        LDSM4(B[0], base + ST_W + bo);
        LDSM4(B[1], base + ST_W + bo + 1280);
#pragma unroll
        for (int mt = 0; mt < 2; ++mt)
#pragma unroll
            for (int nl = 0; nl < 4; ++nl) {
                const int p = nl >> 1;
                const int q = (nl & 1) * 2;
                MMA16816F(c[mt][nl], A[mt], B[p][q], B[p][q + 1]);
            }
    }
}

__global__ void __launch_bounds__(256, 4) gemm_hmma(
    const float* __restrict__ catb, const float* __restrict__ beta,
    const float* __restrict__ gamma)
{
    extern __shared__ __align__(16) char smem[];

    const int nt = blockIdx.x;          // 0..23
    const int bm = blockIdx.y * 64;
    const int grp = nt / 6;
    const int bn  = (nt % 6) * 128;

    const __half* Abase = (grp == 1) ? g_Yf : g_Xf;
    const __half* Wbase = g_Wf + (size_t)grp * NW;

    const int tid  = threadIdx.x;
    const int lane = tid & 31;
    const int warp = tid >> 5;
    const int wm = (warp >> 2) * 32;
    const int wn = (warp & 3) * 32;

    GemmCtx g;
    g.sm0 = (uint32_t)__cvta_generic_to_shared(smem);
    const int r  = tid >> 2;
    const int cb = tid & 3;
    g.offA = (uint32_t)(r * 80 + cb * 16);
    g.Ap  = Abase + (size_t)(bm + r) * Hh + cb * 8;
    g.Wp0 = Wbase + (size_t)(bn + r) * Hh + cb * 8;
    g.Wp1 = g.Wp0 + (size_t)64 * Hh;
    g.a_off = (uint32_t)(((wm + (lane & 15)) * 40 + (lane >> 4) * 8) * 2);
    g.b_off = (uint32_t)(((wn + (lane & 7) + ((lane >> 4) << 3)) * 40
                          + (((lane >> 3) & 1) * 8)) * 2);

    float c[2][4][4];
#pragma unroll
    for (int i = 0; i < 2; ++i)
#pragma unroll
        for (int j = 0; j < 4; ++j)
#pragma unroll
            for (int k = 0; k < 4; ++k) c[i][j][k] = 0.f;

    issue_stage(g, 0, 0);
    issue_stage(g, 1, 1);

    // 3-stage ring, single sync per k-chunk.
#pragma unroll 3
    for (int kc = 0; kc < 24; ++kc) {
        const int s = kc % NSTAGE;
        CP_WAIT(1);                       // group kc landed
        __syncthreads();
        if (kc + 2 < 24) issue_stage(g, (kc + 2) % NSTAGE, kc + 2);
        mma_stage(g, s, c);
    }

    float* OUT;
    const float* bias;
    if (grp == 0)      { OUT = g_A1; bias = catb;    }
    else if (grp == 1) { OUT = g_A2; bias = nullptr; }
    else if (grp == 2) { OUT = g_Bb; bias = beta;    }
    else               { OUT = g_Gg; bias = gamma;   }

    const int gq = lane >> 2;
    const int t2 = (lane & 3) * 2;
#pragma unroll
    for (int mt = 0; mt < 2; ++mt)
#pragma unroll
        for (int ntl = 0; ntl < 4; ++ntl) {
            const int col  = bn + wn + ntl * 8 + t2;
            float2 bv = make_float2(0.f, 0.f);
            if (bias) bv = *(const float2*)(bias + col);
            const int row0 = bm + wm + mt * 16 + gq;
            float2 o0, o1;
            // pre-scale by 0.5 (exact) so the output epilogue skips it
            o0.x = 0.5f * (c[mt][ntl][0] + bv.x); o0.y = 0.5f * (c[mt][ntl][1] + bv.y);
            o1.x = 0.5f * (c[mt][ntl][2] + bv.x); o1.y = 0.5f * (c[mt][ntl][3] + bv.y);
            *(float2*)(OUT + (size_t)row0 * Hh + col)       = o0;
            *(float2*)(OUT + (size_t)(row0 + 8) * Hh + col) = o1;
        }
}

// ---------------- fused output epilogue v4 (write-ceiling plateau) -----------
__global__ void __launch_bounds__(256) epilogue_kernel(float4* __restrict__ out)
{
    __shared__ float4 sA2[8][8], sZ[8][8];

    const int q = blockIdx.x;
    int ic, jc;
    if (q < 16)      { ic = 0; jc = q;           }
    else if (q < 28) { ic = 1; jc = q - 16 + 4;  }
    else if (q < 36) { ic = 2; jc = q - 28 + 8;  }
    else             { ic = 3; jc = q - 36 + 12; }

    const int hc = blockIdx.y;
    const int b  = blockIdx.z;
    const int tid = threadIdx.x;
    const int il = tid >> 3;            // 0..31
    const int hl = tid & 7;

    const int i = ic * 32 + il;
    const int h = hc * 8 + hl;          // float4 lane 0..191

    const float4* __restrict__ A1 = (const float4*)g_A1;
    const float4* __restrict__ A2 = (const float4*)g_A2;
    const float4* __restrict__ Bv = (const float4*)g_Bb;
    const float4* __restrict__ Gv = (const float4*)g_Gg;
    const float4* __restrict__ Z4 = (const float4*)g_Z;

    if (tid < 64) {
        const int jl = tid >> 3;
        const int ry = (b * Ss + jc * 8 + jl) * H4 + h;
        sA2[jl][hl] = A2[ry];
        sZ[jl][hl]  = Z4[ry];
    }

    const int rx = (b * Ss + i) * H4 + h;
    const float4 a1 = A1[rx];
    const float4 bb = Bv[rx];
    const float4 gg = Gv[rx];
    __syncthreads();

    const int rowbase = b * Pp + i * Ss - (i * (i - 1)) / 2 - i + jc * 8;

#pragma unroll
    for (int jl = 0; jl < 8; ++jl) {
        const int j = jc * 8 + jl;
        if (j >= i) {
            const float4 a2 = sA2[jl][hl];
            const float4 zv = sZ[jl][hl];
            float4 o;
            o.x = fmaxf(a1.x + a2.x, 0.f) + zv.x * gg.x + bb.x;
            o.y = fmaxf(a1.y + a2.y, 0.f) + zv.y * gg.y + bb.y;
            o.z = fmaxf(a1.z + a2.z, 0.f) + zv.z * gg.z + bb.z;
            o.w = fmaxf(a1.w + a2.w, 0.f) + zv.w * gg.w + bb.w;
            __stcs(&out[(rowbase + jl) * H4 + h], o);
        }
    }
}

extern "C" void kernel_launch(void* const* d_in, const int* in_sizes, int n_in,
                              void* d_out, int out_size)
{
    const float* x      = (const float*)d_in[0];
    const float* y      = (const float*)d_in[1];
    const float* cat_W  = (const float*)d_in[2];
    const float* cat_b  = (const float*)d_in[3];
    const float* beta   = (const float*)d_in[4];
    const float* gamma  = (const float*)d_in[5];
    const float* beta_W = (const float*)d_in[6];
    const float* gammaW = (const float*)d_in[7];
    float* out = (float*)d_out;

    static int smem_set = 0;
    if (!smem_set) {
        cudaFuncSetAttribute(gemm_hmma, cudaFuncAttributeMaxDynamicSharedMemorySize, SMEM_G);
        smem_set = 1;
    }

    prep_kernel<<<512, 256>>>(x, y, cat_W, beta_W, gammaW);

    dim3 ggrid(24, 16);
    gemm_hmma<<<ggrid, 256, SMEM_G>>>(cat_b, beta, gamma);

    dim3 egrid(40, 24, Bb_);
    epilogue_kernel<<<egrid, 256>>>((float4*)out);
}

// round 14
// speedup vs baseline: 1.0041x; 1.0041x over previous
#include <cuda_runtime.h>
#include <cuda_fp16.h>
#include <cstdint>

#define Hh 768
#define Ss 128
#define Bb_ 8
#define Pp 8256            // S*(S+1)/2
#define NROWS 1024         // B*S
#define H4 192             // H/4
#define NX (NROWS * Hh)    // 786432
#define NW (Hh * Hh)       // 589824 per weight matrix
#define NX4 (NX / 4)       // 196608 float4s in X
#define NW4 (NW / 4)       // 147456 float4s per W

// fp32 activation outputs (pre-scaled by 0.5)
__device__ __align__(16) float g_A1[NX];
__device__ __align__(16) float g_A2[NX];
__device__ __align__(16) float g_Bb[NX];
__device__ __align__(16) float g_Gg[NX];
__device__ __align__(16) float g_Z[NX];     // (y - mean) * rstd (NOT scaled)

// fp16 operands (single precision term — measured rel_err 2.0e-4 < 1e-3)
__device__ __align__(16) __half g_Xf[NX];
__device__ __align__(16) __half g_Yf[NX];
__device__ __align__(16) __half g_Wf[4 * NW];

// ---------------- PTX helpers ----------------

#define CP_ASYNC16(dst, src) \
    asm volatile("cp.async.cg.shared.global [%0], [%1], 16;" \
        :: "r"(dst), "l"(src) : "memory")
#define CP_COMMIT() asm volatile("cp.async.commit_group;" ::: "memory")
#define CP_WAIT(n)  asm volatile("cp.async.wait_group %0;" :: "n"(n) : "memory")

#define LDSM4(R, addr) \
    asm volatile("ldmatrix.sync.aligned.m8n8.x4.shared.b16 {%0,%1,%2,%3}, [%4];" \
        : "=r"((R)[0]), "=r"((R)[1]), "=r"((R)[2]), "=r"((R)[3]) : "r"(addr))

#define MMA16816F(c, a, b0, b1) \
    asm volatile("mma.sync.aligned.m16n8k16.row.col.f32.f16.f16.f32 " \
        "{%0,%1,%2,%3},{%4,%5,%6,%7},{%8,%9},{%0,%1,%2,%3};" \
        : "+f"((c)[0]), "+f"((c)[1]), "+f"((c)[2]), "+f"((c)[3]) \
        : "r"((a)[0]), "r"((a)[1]), "r"((a)[2]), "r"((a)[3]), "r"(b0), "r"(b1))

// float4 -> packed fp16x4
__device__ __forceinline__ uint2 cvt4(float4 v)
{
    __half2 h0 = __float22half2_rn(make_float2(v.x, v.y));
    __half2 h1 = __float22half2_rn(make_float2(v.z, v.w));
    uint2 r;
    r.x = *(uint32_t*)&h0; r.y = *(uint32_t*)&h1;
    return r;
}

// ---------------- merged prep v3 (R12 config) ---------------------------------
// blocks [0,384):  convert X + 4 W matrices, 8 independent float4s per thread
// blocks [384,512): stats + Z + Y conversion (warp per row)
__global__ void __launch_bounds__(256) prep_kernel(
    const float* __restrict__ x, const float* __restrict__ y,
    const float* __restrict__ catW,
    const float* __restrict__ betaW, const float* __restrict__ gammaW)
{
    if (blockIdx.x < 384) {
        const int base4 = blockIdx.x * 2048 + threadIdx.x;   // float4 index
        const float4* src[8];
        __half* dst[8];
#pragma unroll
        for (int k = 0; k < 8; ++k) {
            const int g4 = base4 + k * 256;
            if (g4 < NX4) {
                src[k] = (const float4*)x + g4;
                dst[k] = g_Xf + (size_t)g4 * 4;
            } else {
                const int e4 = g4 - NX4;
                const int g = e4 / NW4;
                const int rem4 = e4 - g * NW4;
                const int r  = rem4 / (Hh / 4);
                const int k4 = rem4 - r * (Hh / 4);
                if (g == 0)      src[k] = (const float4*)(catW + (size_t)r * 2 * Hh) + k4;
                else if (g == 1) src[k] = (const float4*)(catW + (size_t)r * 2 * Hh + Hh) + k4;
                else if (g == 2) src[k] = (const float4*)betaW + rem4;
                else             src[k] = (const float4*)gammaW + rem4;
                dst[k] = g_Wf + (size_t)g * NW + (size_t)rem4 * 4;
            }
        }
        float4 v[8];
#pragma unroll
        for (int k = 0; k < 8; ++k) v[k] = *src[k];           // 8 loads in flight
#pragma unroll
        for (int k = 0; k < 8; ++k) *(uint2*)dst[k] = cvt4(v[k]);
        return;
    }

    // stats for 8 Y rows (warp per row)
    const int rowi = (blockIdx.x - 384) * 8 + (threadIdx.x >> 5);
    const int lane = threadIdx.x & 31;
    const float4* p = (const float4*)(y + (size_t)rowi * Hh);

    float4 v[6];
    float s = 0.f;
#pragma unroll
    for (int q = 0; q < 6; ++q) {
        v[q] = p[lane + 32 * q];
        s += v[q].x + v[q].y + v[q].z + v[q].w;
    }
#pragma unroll
    for (int o = 16; o; o >>= 1) s += __shfl_xor_sync(0xffffffffu, s, o);
    const float m = s * (1.0f / Hh);

    float ss = 0.f;
#pragma unroll
    for (int q = 0; q < 6; ++q) {
        float dx = v[q].x - m, dy = v[q].y - m, dz = v[q].z - m, dw = v[q].w - m;
        ss += dx * dx + dy * dy + dz * dz + dw * dw;
    }
#pragma unroll
    for (int o = 16; o; o >>= 1) ss += __shfl_xor_sync(0xffffffffu, ss, o);
    const float var = ss * (1.0f / Hh);
    float sd = var + 1e-12f;
    sd = sd * sd;                     // reference: std = (var+eps)**2
    const float rr = 1.0f / sd;

    float4* z = (float4*)(g_Z + (size_t)rowi * Hh);
#pragma unroll
    for (int q = 0; q < 6; ++q) {
        float4 o;
        o.x = (v[q].x - m) * rr; o.y = (v[q].y - m) * rr;
        o.z = (v[q].z - m) * rr; o.w = (v[q].w - m) * rr;
        z[lane + 32 * q] = o;
        const size_t eo = (size_t)rowi * Hh + (lane + 32 * q) * 4;
        *(uint2*)(g_Yf + eo) = cvt4(v[q]);
    }
}

// ---------------- HMMA fp16 GEMM: 64x128 tiles, BK=32, 4-stage cp.async ------
// stage: A[64 x 40h] = 5120 B | W[128 x 40h] = 10240 B
#define ST_W    5120
#define STAGE   15360
#define NSTAGE  4
#define SMEM_G  (NSTAGE * STAGE)

struct GemmCtx {
    uint32_t sm0;
    uint32_t offA, a_off, b_off;
    const __half *Ap, *Wp0, *Wp1;
};

__device__ __forceinline__ void issue_stage(const GemmCtx& g, int s, int kc)
{
    const uint32_t b0 = g.sm0 + s * STAGE;
    const int ko = kc * 32;
    CP_ASYNC16(b0 + g.offA,                g.Ap  + ko);
    CP_ASYNC16(b0 + ST_W + g.offA,         g.Wp0 + ko);
    CP_ASYNC16(b0 + ST_W + g.offA + 5120,  g.Wp1 + ko);
    CP_COMMIT();
}

__device__ __forceinline__ void mma_stage(const GemmCtx& g, int s, float c[2][4][4])
{
    const uint32_t base = g.sm0 + s * STAGE;
#pragma unroll
    for (int kh = 0; kh < 2; ++kh) {
        const uint32_t ao = g.a_off + kh * 32;
        const uint32_t bo = g.b_off + kh * 32;
        uint32_t A[2][4], B[2][4];
        LDSM4(A[0], base + ao);
        LDSM4(A[1], base + ao + 1280);
        LDSM4(B[0], base + ST_W + bo);
        LDSM4(B[1], base + ST_W + bo + 1280);
#pragma unroll
        for (int mt = 0; mt < 2; ++mt)
#pragma unroll
            for (int nl = 0; nl < 4; ++nl) {
                const int p = nl >> 1;
                const int q = (nl & 1) * 2;
                MMA16816F(c[mt][nl], A[mt], B[p][q], B[p][q + 1]);
            }
    }
}

__global__ void __launch_bounds__(256, 3) gemm_hmma(
    const float* __restrict__ catb, const float* __restrict__ beta,
    const float* __restrict__ gamma)
{
    extern __shared__ __align__(16) char smem[];

    const int nt = blockIdx.x;          // 0..23
    const int bm = blockIdx.y * 64;
    const int grp = nt / 6;
    const int bn  = (nt % 6) * 128;

    const __half* Abase = (grp == 1) ? g_Yf : g_Xf;
    const __half* Wbase = g_Wf + (size_t)grp * NW;

    const int tid  = threadIdx.x;
    const int lane = tid & 31;
    const int warp = tid >> 5;
    const int wm = (warp >> 2) * 32;
    const int wn = (warp & 3) * 32;

    GemmCtx g;
    g.sm0 = (uint32_t)__cvta_generic_to_shared(smem);
    const int r  = tid >> 2;
    const int cb = tid & 3;
    g.offA = (uint32_t)(r * 80 + cb * 16);
    g.Ap  = Abase + (size_t)(bm + r) * Hh + cb * 8;
    g.Wp0 = Wbase + (size_t)(bn + r) * Hh + cb * 8;
    g.Wp1 = g.Wp0 + (size_t)64 * Hh;
    g.a_off = (uint32_t)(((wm + (lane & 15)) * 40 + (lane >> 4) * 8) * 2);
    g.b_off = (uint32_t)(((wn + (lane & 7) + ((lane >> 4) << 3)) * 40
                          + (((lane >> 3) & 1) * 8)) * 2);

    float c[2][4][4];
#pragma unroll
    for (int i = 0; i < 2; ++i)
#pragma unroll
        for (int j = 0; j < 4; ++j)
#pragma unroll
            for (int k = 0; k < 4; ++k) c[i][j][k] = 0.f;

    issue_stage(g, 0, 0);
    issue_stage(g, 1, 1);
    issue_stage(g, 2, 2);

    // 4-stage ring, single sync per k-chunk, prefetch distance 3.
    // Top-of-iter sync guarantees all warps consumed slot (kc-1), so issuing
    // kc+3 into slot (kc+3)%4 == (kc-1)%4 right after it is safe.
    // Tail: groups stop being issued after kc=20, so kc>=21 fully drains
    // (CP_WAIT(0)) — guarantees group kc has landed before mma reads it.
#pragma unroll 4
    for (int kc = 0; kc < 24; ++kc) {
        const int s = kc % NSTAGE;
        if (kc < 21) { CP_WAIT(2); } else { CP_WAIT(0); }
        __syncthreads();
        if (kc + 3 < 24) issue_stage(g, (kc + 3) % NSTAGE, kc + 3);
        mma_stage(g, s, c);
    }

    float* OUT;
    const float* bias;
    if (grp == 0)      { OUT = g_A1; bias = catb;    }
    else if (grp == 1) { OUT = g_A2; bias = nullptr; }
    else if (grp == 2) { OUT = g_Bb; bias = beta;    }
    else               { OUT = g_Gg; bias = gamma;   }

    const int gq = lane >> 2;
    const int t2 = (lane & 3) * 2;
#pragma unroll
    for (int mt = 0; mt < 2; ++mt)
#pragma unroll
        for (int ntl = 0; ntl < 4; ++ntl) {
            const int col  = bn + wn + ntl * 8 + t2;
            float2 bv = make_float2(0.f, 0.f);
            if (bias) bv = *(const float2*)(bias + col);
            const int row0 = bm + wm + mt * 16 + gq;
            float2 o0, o1;
            // pre-scale by 0.5 (exact) so the output epilogue skips it
            o0.x = 0.5f * (c[mt][ntl][0] + bv.x); o0.y = 0.5f * (c[mt][ntl][1] + bv.y);
            o1.x = 0.5f * (c[mt][ntl][2] + bv.x); o1.y = 0.5f * (c[mt][ntl][3] + bv.y);
            *(float2*)(OUT + (size_t)row0 * Hh + col)       = o0;
            *(float2*)(OUT + (size_t)(row0 + 8) * Hh + col) = o1;
        }
}

// ---------------- fused output epilogue v4 (write-ceiling plateau) -----------
__global__ void __launch_bounds__(256) epilogue_kernel(float4* __restrict__ out)
{
    __shared__ float4 sA2[8][8], sZ[8][8];

    const int q = blockIdx.x;
    int ic, jc;
    if (q < 16)      { ic = 0; jc = q;           }
    else if (q < 28) { ic = 1; jc = q - 16 + 4;  }
    else if (q < 36) { ic = 2; jc = q - 28 + 8;  }
    else             { ic = 3; jc = q - 36 + 12; }

    const int hc = blockIdx.y;
    const int b  = blockIdx.z;
    const int tid = threadIdx.x;
    const int il = tid >> 3;            // 0..31
    const int hl = tid & 7;

    const int i = ic * 32 + il;
    const int h = hc * 8 + hl;          // float4 lane 0..191

    const float4* __restrict__ A1 = (const float4*)g_A1;
    const float4* __restrict__ A2 = (const float4*)g_A2;
    const float4* __restrict__ Bv = (const float4*)g_Bb;
    const float4* __restrict__ Gv = (const float4*)g_Gg;
    const float4* __restrict__ Z4 = (const float4*)g_Z;

    if (tid < 64) {
        const int jl = tid >> 3;
        const int ry = (b * Ss + jc * 8 + jl) * H4 + h;
        sA2[jl][hl] = A2[ry];
        sZ[jl][hl]  = Z4[ry];
    }

    const int rx = (b * Ss + i) * H4 + h;
    const float4 a1 = A1[rx];
    const float4 bb = Bv[rx];
    const float4 gg = Gv[rx];
    __syncthreads();

    const int rowbase = b * Pp + i * Ss - (i * (i - 1)) / 2 - i + jc * 8;

#pragma unroll
    for (int jl = 0; jl < 8; ++jl) {
        const int j = jc * 8 + jl;
        if (j >= i) {
            const float4 a2 = sA2[jl][hl];
            const float4 zv = sZ[jl][hl];
            float4 o;
            o.x = fmaxf(a1.x + a2.x, 0.f) + zv.x * gg.x + bb.x;
            o.y = fmaxf(a1.y + a2.y, 0.f) + zv.y * gg.y + bb.y;
            o.z = fmaxf(a1.z + a2.z, 0.f) + zv.z * gg.z + bb.z;
            o.w = fmaxf(a1.w + a2.w, 0.f) + zv.w * gg.w + bb.w;
            __stcs(&out[(rowbase + jl) * H4 + h], o);
        }
    }
}

extern "C" void kernel_launch(void* const* d_in, const int* in_sizes, int n_in,
                              void* d_out, int out_size)
{
    const float* x      = (const float*)d_in[0];
    const float* y      = (const float*)d_in[1];
    const float* cat_W  = (const float*)d_in[2];
    const float* cat_b  = (const float*)d_in[3];
    const float* beta   = (const float*)d_in[4];
    const float* gamma  = (const float*)d_in[5];
    const float* beta_W = (const float*)d_in[6];
    const float* gammaW = (const float*)d_in[7];
    float* out = (float*)d_out;

    static int smem_set = 0;
    if (!smem_set) {
        cudaFuncSetAttribute(gemm_hmma, cudaFuncAttributeMaxDynamicSharedMemorySize, SMEM_G);
        smem_set = 1;
    }

    prep_kernel<<<512, 256>>>(x, y, cat_W, beta_W, gammaW);

    dim3 ggrid(24, 16);
    gemm_hmma<<<ggrid, 256, SMEM_G>>>(cat_b, beta, gamma);

    dim3 egrid(40, 24, Bb_);
    epilogue_kernel<<<egrid, 256>>>((float4*)out);
}